// round 6
// baseline (speedup 1.0000x reference)
#include <cuda_runtime.h>
#include <cuda_bf16.h>
#include <cstdint>
#include <math.h>

#define NPTS 8192
#define KCEN 128
#define DDIM 512

// Pre-converted centroids (bf16) + centroid sq-norms.
__device__ __nv_bfloat16 g_cb[KCEN * DDIM];   // 128 KB
__device__ float g_cnorm[KCEN];

// ---------------- SMEM layout (main kernel, dynamic) ----------------
// stride per row: 128 bf16 = 256B, padded to 272B (conflict-free ldmatrix)
#define SB      272u
#define SM_XN   0u            // 32 floats
#define SM_CN   128u          // 128 floats
#define SM_A0   1024u         // 32*272 = 8704
#define SM_A1   9728u
#define SM_B0   18432u        // 128*272 = 34816
#define SM_B1   53248u
#define SM_TOTAL 88064u       // fits 2 CTAs/SM (176 KB < 228 KB)

__device__ __forceinline__ uint32_t smem_u32_of(const void* p) {
    uint32_t a;
    asm("{ .reg .u64 t; cvta.to.shared.u64 t, %1; cvt.u32.u64 %0, t; }" : "=r"(a) : "l"(p));
    return a;
}

#define LDMATRIX_X4(r0, r1, r2, r3, addr) \
    asm volatile("ldmatrix.sync.aligned.m8n8.x4.shared.b16 {%0,%1,%2,%3}, [%4];" \
        : "=r"(r0), "=r"(r1), "=r"(r2), "=r"(r3) : "r"(addr))

#define MMA_BF16(c, a, b0, b1) \
    asm volatile("mma.sync.aligned.m16n8k16.row.col.f32.bf16.bf16.f32 " \
        "{%0,%1,%2,%3}, {%4,%5,%6,%7}, {%8,%9}, {%0,%1,%2,%3};" \
        : "+f"((c)[0]), "+f"((c)[1]), "+f"((c)[2]), "+f"((c)[3]) \
        : "r"((a)[0]), "r"((a)[1]), "r"((a)[2]), "r"((a)[3]), "r"(b0), "r"(b1))

#define CP_ASYNC16(dst, src) \
    asm volatile("cp.async.cg.shared.global [%0], [%1], 16;" :: "r"(dst), "l"(src) : "memory")
#define CP_COMMIT() asm volatile("cp.async.commit_group;" ::: "memory")
#define CP_WAIT(n)  asm volatile("cp.async.wait_group %0;" :: "n"(n) : "memory")

// ---------------------------------------------------------------------------
// Prepass: centroids fp32 -> bf16 global + sq-norms. One warp per centroid.
// ---------------------------------------------------------------------------
__global__ __launch_bounds__(256) void cen_prep_kernel(const float* __restrict__ cen) {
    int warp = (blockIdx.x * 256 + threadIdx.x) >> 5;
    int lane = threadIdx.x & 31;
    if (warp >= KCEN) return;
    const float4* p = reinterpret_cast<const float4*>(cen + (size_t)warp * DDIM);
    float s = 0.0f;
#pragma unroll
    for (int j = 0; j < 4; j++) {
        float4 v = p[lane + j * 32];
        __nv_bfloat162 lo = __float22bfloat162_rn(make_float2(v.x, v.y));
        __nv_bfloat162 hi = __float22bfloat162_rn(make_float2(v.z, v.w));
        uint2 u;
        u.x = *reinterpret_cast<uint32_t*>(&lo);
        u.y = *reinterpret_cast<uint32_t*>(&hi);
        *reinterpret_cast<uint2*>(g_cb + (size_t)warp * DDIM + (lane + j * 32) * 4) = u;
        s = fmaf(v.x, v.x, fmaf(v.y, v.y, fmaf(v.z, v.z, fmaf(v.w, v.w, s))));
    }
#pragma unroll
    for (int o = 16; o > 0; o >>= 1) s += __shfl_xor_sync(0xffffffffu, s, o);
    if (lane == 0) g_cnorm[warp] = s;
}

// ---------------------------------------------------------------------------
// Main kernel helpers (CTA tile: 32 rows x 128 centroids)
// ---------------------------------------------------------------------------
// Stage A chunk (32 rows x 128 cols fp32) into registers. Warp w owns rows w+8i.
__device__ __forceinline__ void ldgA(const float* __restrict__ x, int rowBase, int chunk,
                                     int wid, int lane, float4 v[4]) {
#pragma unroll
    for (int i = 0; i < 4; i++) {
        int row = wid + i * 8;
        v[i] = *reinterpret_cast<const float4*>(
            x + (size_t)(rowBase + row) * DDIM + chunk * 128 + lane * 4);
    }
}

// Convert staged A regs -> bf16 smem buffer; fuse row sq-norm accumulation.
__device__ __forceinline__ void stsA(char* smem, uint32_t aoff, float* sxn,
                                     int wid, int lane, const float4 v[4]) {
#pragma unroll
    for (int i = 0; i < 4; i++) {
        int row = wid + i * 8;
        __nv_bfloat162 lo = __float22bfloat162_rn(make_float2(v[i].x, v[i].y));
        __nv_bfloat162 hi = __float22bfloat162_rn(make_float2(v[i].z, v[i].w));
        uint2 u;
        u.x = *reinterpret_cast<uint32_t*>(&lo);
        u.y = *reinterpret_cast<uint32_t*>(&hi);
        *reinterpret_cast<uint2*>(smem + aoff + (uint32_t)row * SB + (uint32_t)lane * 8u) = u;
        float s = fmaf(v[i].x, v[i].x, fmaf(v[i].y, v[i].y,
                  fmaf(v[i].z, v[i].z, v[i].w * v[i].w)));
#pragma unroll
        for (int o = 16; o > 0; o >>= 1) s += __shfl_xor_sync(0xffffffffu, s, o);
        if (lane == 0) sxn[row] += s;   // warp w owns row w+8i in every chunk: no race
    }
}

// Async-copy B chunk (128 rows x 128 cols bf16) from pre-converted global.
__device__ __forceinline__ void cpB(uint32_t su, uint32_t boff, int chunk, int tid) {
#pragma unroll
    for (int i = 0; i < 8; i++) {
        int unit = tid + i * 256;            // 2048 16B units
        int row = unit >> 4;
        int u   = unit & 15;
        const __nv_bfloat16* src = g_cb + (size_t)row * DDIM + chunk * 128 + u * 8;
        uint32_t dst = su + boff + (uint32_t)row * SB + (uint32_t)u * 16u;
        CP_ASYNC16(dst, src);
    }
}

// MMA over one K=128 chunk: warp tile 16(m) x 32(n), 8 k-steps of 16.
__device__ __forceinline__ void mma_chunk(uint32_t su, uint32_t aoff, uint32_t boff,
                                          int mbase, int nbase, int lane,
                                          float acc[4][4]) {
    const uint32_t koff = (uint32_t)(lane >> 4) * 16u;
    const int lrow = lane & 15;
    uint32_t aaddr = su + aoff + (uint32_t)(mbase + lrow) * SB + koff;
    uint32_t baddr[2];
#pragma unroll
    for (int f = 0; f < 2; f++)
        baddr[f] = su + boff + (uint32_t)(nbase + f * 16 + lrow) * SB + koff;

#pragma unroll
    for (int kk = 0; kk < 8; kk++) {
        const uint32_t kb = (uint32_t)kk * 32u;
        uint32_t a[4], br[2][4];
        LDMATRIX_X4(a[0], a[1], a[2], a[3], aaddr + kb);
#pragma unroll
        for (int f = 0; f < 2; f++)
            LDMATRIX_X4(br[f][0], br[f][1], br[f][2], br[f][3], baddr[f] + kb);
#pragma unroll
        for (int fn = 0; fn < 4; fn++) {
            const int bi = fn >> 1, sub = fn & 1;
            MMA_BF16(acc[fn], a, br[bi][sub], br[bi][sub + 2]);
        }
    }
}

// ---------------------------------------------------------------------------
// Main kernel: 256 CTAs x 256 thr (2 CTAs/SM), CTA tile 32 x 128, K piped.
// ---------------------------------------------------------------------------
__global__ __launch_bounds__(256, 2) void kmeans_dist_kernel(const float* __restrict__ x,
                                                             float* __restrict__ out) {
    extern __shared__ char smem[];
    const uint32_t su = smem_u32_of(smem);
    const int tid  = threadIdx.x;
    const int wid  = tid >> 5;
    const int lane = tid & 31;
    const int rowBase = blockIdx.x * 32;

    float* sxn = reinterpret_cast<float*>(smem + SM_XN);
    float* scn = reinterpret_cast<float*>(smem + SM_CN);
    if (tid < 32)  sxn[tid] = 0.0f;
    if (tid >= 64 && tid < 192) scn[tid - 64] = g_cnorm[tid - 64];
    __syncthreads();

    const int mbase = (wid >> 2) * 16;     // 0..16
    const int nbase = (wid & 3) * 32;      // 0..96

    float acc[4][4];
#pragma unroll
    for (int j = 0; j < 4; j++)
#pragma unroll
        for (int q = 0; q < 4; q++) acc[j][q] = 0.0f;

    float4 st[4];

    // ---- prologue ----
    ldgA(x, rowBase, 0, wid, lane, st);
    cpB(su, SM_B0, 0, tid); CP_COMMIT();          // g0
    cpB(su, SM_B1, 1, tid); CP_COMMIT();          // g1
    stsA(smem, SM_A0, sxn, wid, lane, st);
    CP_WAIT(1); __syncthreads();                  // B0 + A0 ready

    // ---- chunk 0 ----
    ldgA(x, rowBase, 1, wid, lane, st);           // overlaps MMA
    mma_chunk(su, SM_A0, SM_B0, mbase, nbase, lane, acc);
    __syncthreads();                              // done reading A0/B0
    stsA(smem, SM_A1, sxn, wid, lane, st);
    cpB(su, SM_B0, 2, tid); CP_COMMIT();          // g2 (B0 free now)
    CP_WAIT(1); __syncthreads();                  // B1 + A1 ready

    // ---- chunk 1 ----
    ldgA(x, rowBase, 2, wid, lane, st);
    mma_chunk(su, SM_A1, SM_B1, mbase, nbase, lane, acc);
    __syncthreads();
    stsA(smem, SM_A0, sxn, wid, lane, st);
    cpB(su, SM_B1, 3, tid); CP_COMMIT();          // g3
    CP_WAIT(1); __syncthreads();                  // B0(c2) + A0(c2) ready

    // ---- chunk 2 ----
    ldgA(x, rowBase, 3, wid, lane, st);
    mma_chunk(su, SM_A0, SM_B0, mbase, nbase, lane, acc);
    __syncthreads();
    stsA(smem, SM_A1, sxn, wid, lane, st);
    CP_WAIT(0); __syncthreads();                  // B1(c3) + A1(c3) ready

    // ---- chunk 3 ----
    mma_chunk(su, SM_A1, SM_B1, mbase, nbase, lane, acc);

    // ---- epilogue: dist = sqrt(max(xn + cn - 2*dot, 0)) ----
    const int qrow = lane >> 2;
    const int qcol = (lane & 3) * 2;
    const int r0 = mbase + qrow;
    const float xn0 = sxn[r0];
    const float xn1 = sxn[r0 + 8];
#pragma unroll
    for (int fn = 0; fn < 4; fn++) {
        const int c = nbase + fn * 8 + qcol;
        const float cn0 = scn[c];
        const float cn1 = scn[c + 1];
        float2 o0, o1;
        o0.x = sqrtf(fmaxf(xn0 + cn0 - 2.0f * acc[fn][0], 0.0f));
        o0.y = sqrtf(fmaxf(xn0 + cn1 - 2.0f * acc[fn][1], 0.0f));
        o1.x = sqrtf(fmaxf(xn1 + cn0 - 2.0f * acc[fn][2], 0.0f));
        o1.y = sqrtf(fmaxf(xn1 + cn1 - 2.0f * acc[fn][3], 0.0f));
        *reinterpret_cast<float2*>(out + (size_t)(rowBase + r0) * KCEN + c)     = o0;
        *reinterpret_cast<float2*>(out + (size_t)(rowBase + r0 + 8) * KCEN + c) = o1;
    }
}

extern "C" void kernel_launch(void* const* d_in, const int* in_sizes, int n_in,
                              void* d_out, int out_size) {
    const float* x   = (const float*)d_in[0];
    const float* cen = (const float*)d_in[1];
    float* out = (float*)d_out;

    cudaFuncSetAttribute(kmeans_dist_kernel,
                         cudaFuncAttributeMaxDynamicSharedMemorySize, SM_TOTAL);

    cen_prep_kernel<<<16, 256>>>(cen);                       // 128 warps, one per centroid
    kmeans_dist_kernel<<<256, 256, SM_TOTAL>>>(x, out);      // 8192/32 rows
}

// round 8
// speedup vs baseline: 1.0602x; 1.0602x over previous
#include <cuda_runtime.h>
#include <cuda_bf16.h>
#include <cstdint>
#include <math.h>

#define NPTS 8192
#define KCEN 128
#define DDIM 512

// Pre-converted bf16 copies + sq-norms (filled by prep_kernel).
__device__ __nv_bfloat16 g_xb[NPTS * DDIM];   // 8 MB
__device__ __nv_bfloat16 g_cb[KCEN * DDIM];   // 128 KB
__device__ float g_xnorm[NPTS];
__device__ float g_cnorm[KCEN];

// ---------------- SMEM layout (main kernel, dynamic) ----------------
// row stride: 128 bf16 = 256B, padded to 272B (conflict-free ldmatrix)
#define SB      272u
#define SM_XN   0u            // 64 floats
#define SM_CN   256u          // 128 floats
#define SM_A0   1024u         // 64*272  = 17408
#define SM_A1   18432u
#define SM_B0   35840u        // 128*272 = 34816
#define SM_B1   70656u
#define SM_TOTAL 105472u      // x2 CTAs = 210944 <= 227KB

__device__ __forceinline__ uint32_t smem_u32_of(const void* p) {
    uint32_t a;
    asm("{ .reg .u64 t; cvta.to.shared.u64 t, %1; cvt.u32.u64 %0, t; }" : "=r"(a) : "l"(p));
    return a;
}

#define LDMATRIX_X4(r0, r1, r2, r3, addr) \
    asm volatile("ldmatrix.sync.aligned.m8n8.x4.shared.b16 {%0,%1,%2,%3}, [%4];" \
        : "=r"(r0), "=r"(r1), "=r"(r2), "=r"(r3) : "r"(addr))

#define MMA_BF16(c, a, b0, b1) \
    asm volatile("mma.sync.aligned.m16n8k16.row.col.f32.bf16.bf16.f32 " \
        "{%0,%1,%2,%3}, {%4,%5,%6,%7}, {%8,%9}, {%0,%1,%2,%3};" \
        : "+f"((c)[0]), "+f"((c)[1]), "+f"((c)[2]), "+f"((c)[3]) \
        : "r"((a)[0]), "r"((a)[1]), "r"((a)[2]), "r"((a)[3]), "r"(b0), "r"(b1))

#define CP_ASYNC16(dst, src) \
    asm volatile("cp.async.cg.shared.global [%0], [%1], 16;" :: "r"(dst), "l"(src) : "memory")
#define CP_COMMIT() asm volatile("cp.async.commit_group;" ::: "memory")
#define CP_WAIT(n)  asm volatile("cp.async.wait_group %0;" :: "n"(n) : "memory")

// ---------------------------------------------------------------------------
// Prepass: fp32 -> bf16 for x AND centroids, plus sq-norms. Warp per row.
// 8192 + 128 = 8320 warps -> 1040 CTAs x 256 thr.
// ---------------------------------------------------------------------------
__global__ __launch_bounds__(256) void prep_kernel(const float* __restrict__ x,
                                                   const float* __restrict__ cen) {
    int warp = (blockIdx.x * 256 + threadIdx.x) >> 5;
    int lane = threadIdx.x & 31;

    const float* src;
    __nv_bfloat16* dst;
    float* nd;
    if (warp < NPTS) {
        src = x + (size_t)warp * DDIM;
        dst = g_xb + (size_t)warp * DDIM;
        nd  = g_xnorm + warp;
    } else if (warp < NPTS + KCEN) {
        int r = warp - NPTS;
        src = cen + (size_t)r * DDIM;
        dst = g_cb + (size_t)r * DDIM;
        nd  = g_cnorm + r;
    } else return;

    const float4* p = reinterpret_cast<const float4*>(src);
    float s = 0.0f;
#pragma unroll
    for (int j = 0; j < 4; j++) {
        float4 v = p[lane + j * 32];
        __nv_bfloat162 lo = __float22bfloat162_rn(make_float2(v.x, v.y));
        __nv_bfloat162 hi = __float22bfloat162_rn(make_float2(v.z, v.w));
        uint2 u;
        u.x = *reinterpret_cast<uint32_t*>(&lo);
        u.y = *reinterpret_cast<uint32_t*>(&hi);
        reinterpret_cast<uint2*>(dst)[lane + j * 32] = u;
        s = fmaf(v.x, v.x, fmaf(v.y, v.y, fmaf(v.z, v.z, fmaf(v.w, v.w, s))));
    }
#pragma unroll
    for (int o = 16; o > 0; o >>= 1) s += __shfl_xor_sync(0xffffffffu, s, o);
    if (lane == 0) *nd = s;
}

// ---------------------------------------------------------------------------
// Main kernel helpers: pure cp.async loads of bf16 chunks.
// ---------------------------------------------------------------------------
__device__ __forceinline__ void cpA(uint32_t su, uint32_t aoff, int rowBase,
                                    int chunk, int tid) {
    // 64 rows x 128 bf16 = 1024 x 16B units; 4 per thread
#pragma unroll
    for (int i = 0; i < 4; i++) {
        int unit = tid + i * 256;
        int row = unit >> 4;
        int u   = unit & 15;
        const __nv_bfloat16* src = g_xb + (size_t)(rowBase + row) * DDIM + chunk * 128 + u * 8;
        CP_ASYNC16(su + aoff + (uint32_t)row * SB + (uint32_t)u * 16u, src);
    }
}

__device__ __forceinline__ void cpB(uint32_t su, uint32_t boff, int chunk, int tid) {
    // 128 rows x 128 bf16 = 2048 x 16B units; 8 per thread
#pragma unroll
    for (int i = 0; i < 8; i++) {
        int unit = tid + i * 256;
        int row = unit >> 4;
        int u   = unit & 15;
        const __nv_bfloat16* src = g_cb + (size_t)row * DDIM + chunk * 128 + u * 8;
        CP_ASYNC16(su + boff + (uint32_t)row * SB + (uint32_t)u * 16u, src);
    }
}

// MMA over one K=128 chunk: warp tile 32(m) x 32(n), 8 k-steps of 16.
__device__ __forceinline__ void mma_chunk(uint32_t su, uint32_t aoff, uint32_t boff,
                                          int mbase, int nbase, int lane,
                                          float acc[2][4][4]) {
    const uint32_t koff = (uint32_t)(lane >> 4) * 16u;
    const int lrow = lane & 15;
    uint32_t aaddr[2], baddr[2];
#pragma unroll
    for (int f = 0; f < 2; f++) {
        aaddr[f] = su + aoff + (uint32_t)(mbase + f * 16 + lrow) * SB + koff;
        baddr[f] = su + boff + (uint32_t)(nbase + f * 16 + lrow) * SB + koff;
    }
#pragma unroll
    for (int kk = 0; kk < 8; kk++) {
        const uint32_t kb = (uint32_t)kk * 32u;
        uint32_t a[2][4], br[2][4];
#pragma unroll
        for (int f = 0; f < 2; f++)
            LDMATRIX_X4(a[f][0], a[f][1], a[f][2], a[f][3], aaddr[f] + kb);
#pragma unroll
        for (int f = 0; f < 2; f++)
            LDMATRIX_X4(br[f][0], br[f][1], br[f][2], br[f][3], baddr[f] + kb);
#pragma unroll
        for (int fm = 0; fm < 2; fm++)
#pragma unroll
            for (int fn = 0; fn < 4; fn++) {
                const int bi = fn >> 1, sub = fn & 1;
                MMA_BF16(acc[fm][fn], a[fm], br[bi][sub], br[bi][sub + 2]);
            }
    }
}

// ---------------------------------------------------------------------------
// Main kernel: 128 CTAs x 256 thr, 2 CTAs/SM, tile 64 x 128, K piped (4x128).
// ---------------------------------------------------------------------------
__global__ __launch_bounds__(256, 2) void kmeans_dist_kernel(float* __restrict__ out) {
    extern __shared__ char smem[];
    const uint32_t su = smem_u32_of(smem);
    const int tid  = threadIdx.x;
    const int wid  = tid >> 5;
    const int lane = tid & 31;
    const int rowBase = blockIdx.x * 64;

    float* sxn = reinterpret_cast<float*>(smem + SM_XN);
    float* scn = reinterpret_cast<float*>(smem + SM_CN);
    if (tid < 64)  sxn[tid] = g_xnorm[rowBase + tid];
    if (tid >= 128 && tid < 256) scn[tid - 128] = g_cnorm[tid - 128];

    const int mbase = (wid >> 2) * 32;
    const int nbase = (wid & 3) * 32;

    float acc[2][4][4];
#pragma unroll
    for (int i = 0; i < 2; i++)
#pragma unroll
        for (int j = 0; j < 4; j++)
#pragma unroll
            for (int q = 0; q < 4; q++) acc[i][j][q] = 0.0f;

    // ---- prologue: two chunks in flight ----
    cpA(su, SM_A0, rowBase, 0, tid);
    cpB(su, SM_B0, 0, tid); CP_COMMIT();
    cpA(su, SM_A1, rowBase, 1, tid);
    cpB(su, SM_B1, 1, tid); CP_COMMIT();

    // ---- chunk 0 ----
    CP_WAIT(1); __syncthreads();
    mma_chunk(su, SM_A0, SM_B0, mbase, nbase, lane, acc);
    __syncthreads();
    cpA(su, SM_A0, rowBase, 2, tid);
    cpB(su, SM_B0, 2, tid); CP_COMMIT();

    // ---- chunk 1 ----
    CP_WAIT(1); __syncthreads();
    mma_chunk(su, SM_A1, SM_B1, mbase, nbase, lane, acc);
    __syncthreads();
    cpA(su, SM_A1, rowBase, 3, tid);
    cpB(su, SM_B1, 3, tid); CP_COMMIT();

    // ---- chunk 2 ----
    CP_WAIT(1); __syncthreads();
    mma_chunk(su, SM_A0, SM_B0, mbase, nbase, lane, acc);

    // ---- chunk 3 ----
    CP_WAIT(0); __syncthreads();
    mma_chunk(su, SM_A1, SM_B1, mbase, nbase, lane, acc);

    // ---- epilogue: dist = sqrt(max(xn + cn - 2*dot, 0)) ----
    const int qrow = lane >> 2;
    const int qcol = (lane & 3) * 2;
#pragma unroll
    for (int fm = 0; fm < 2; fm++) {
        const int r0 = mbase + fm * 16 + qrow;
        const float xn0 = sxn[r0];
        const float xn1 = sxn[r0 + 8];
#pragma unroll
        for (int fn = 0; fn < 4; fn++) {
            const int c = nbase + fn * 8 + qcol;
            const float cn0 = scn[c];
            const float cn1 = scn[c + 1];
            float2 o0, o1;
            o0.x = sqrtf(fmaxf(xn0 + cn0 - 2.0f * acc[fm][fn][0], 0.0f));
            o0.y = sqrtf(fmaxf(xn0 + cn1 - 2.0f * acc[fm][fn][1], 0.0f));
            o1.x = sqrtf(fmaxf(xn1 + cn0 - 2.0f * acc[fm][fn][2], 0.0f));
            o1.y = sqrtf(fmaxf(xn1 + cn1 - 2.0f * acc[fm][fn][3], 0.0f));
            *reinterpret_cast<float2*>(out + (size_t)(rowBase + r0) * KCEN + c)     = o0;
            *reinterpret_cast<float2*>(out + (size_t)(rowBase + r0 + 8) * KCEN + c) = o1;
        }
    }
}

extern "C" void kernel_launch(void* const* d_in, const int* in_sizes, int n_in,
                              void* d_out, int out_size) {
    const float* x   = (const float*)d_in[0];
    const float* cen = (const float*)d_in[1];
    float* out = (float*)d_out;

    cudaFuncSetAttribute(kmeans_dist_kernel,
                         cudaFuncAttributeMaxDynamicSharedMemorySize, SM_TOTAL);

    prep_kernel<<<1040, 256>>>(x, cen);               // 8320 warps, one per row
    kmeans_dist_kernel<<<128, 256, SM_TOTAL>>>(out);  // 8192/64 rows
}

// round 9
// speedup vs baseline: 1.1404x; 1.0756x over previous
#include <cuda_runtime.h>
#include <cuda_bf16.h>
#include <cstdint>
#include <math.h>

#define NPTS 8192
#define KCEN 128
#define DDIM 512

// Pre-converted centroids (bf16) + centroid sq-norms.
__device__ __nv_bfloat16 g_cb[KCEN * DDIM];   // 128 KB
__device__ float g_cnorm[KCEN];

// ---------------- SMEM layout (main kernel, dynamic) ----------------
// row stride: 128 bf16 = 256B, padded to 272B (conflict-free ldmatrix)
#define SB      272u
#define SM_XN   0u            // 64 floats
#define SM_CN   256u          // 128 floats
#define SM_A0   1024u         // 64*272  = 17408
#define SM_A1   18432u
#define SM_B0   35840u        // 128*272 = 34816
#define SM_B1   70656u
#define SM_TOTAL 105472u

__device__ __forceinline__ uint32_t smem_u32_of(const void* p) {
    uint32_t a;
    asm("{ .reg .u64 t; cvta.to.shared.u64 t, %1; cvt.u32.u64 %0, t; }" : "=r"(a) : "l"(p));
    return a;
}

#define LDMATRIX_X4(r0, r1, r2, r3, addr) \
    asm volatile("ldmatrix.sync.aligned.m8n8.x4.shared.b16 {%0,%1,%2,%3}, [%4];" \
        : "=r"(r0), "=r"(r1), "=r"(r2), "=r"(r3) : "r"(addr))

#define MMA_BF16(c, a, b0, b1) \
    asm volatile("mma.sync.aligned.m16n8k16.row.col.f32.bf16.bf16.f32 " \
        "{%0,%1,%2,%3}, {%4,%5,%6,%7}, {%8,%9}, {%0,%1,%2,%3};" \
        : "+f"((c)[0]), "+f"((c)[1]), "+f"((c)[2]), "+f"((c)[3]) \
        : "r"((a)[0]), "r"((a)[1]), "r"((a)[2]), "r"((a)[3]), "r"(b0), "r"(b1))

#define CP_ASYNC16(dst, src) \
    asm volatile("cp.async.cg.shared.global [%0], [%1], 16;" :: "r"(dst), "l"(src) : "memory")
#define CP_COMMIT() asm volatile("cp.async.commit_group;" ::: "memory")
#define CP_WAIT(n)  asm volatile("cp.async.wait_group %0;" :: "n"(n) : "memory")

// ---------------------------------------------------------------------------
// Prepass: centroids fp32 -> bf16 global + sq-norms. One warp per centroid.
// ---------------------------------------------------------------------------
__global__ __launch_bounds__(256) void cen_prep_kernel(const float* __restrict__ cen) {
    int warp = (blockIdx.x * 256 + threadIdx.x) >> 5;
    int lane = threadIdx.x & 31;
    if (warp >= KCEN) return;
    const float4* p = reinterpret_cast<const float4*>(cen + (size_t)warp * DDIM);
    float s = 0.0f;
#pragma unroll
    for (int j = 0; j < 4; j++) {
        float4 v = p[lane + j * 32];
        __nv_bfloat162 lo = __float22bfloat162_rn(make_float2(v.x, v.y));
        __nv_bfloat162 hi = __float22bfloat162_rn(make_float2(v.z, v.w));
        uint2 u;
        u.x = *reinterpret_cast<uint32_t*>(&lo);
        u.y = *reinterpret_cast<uint32_t*>(&hi);
        *reinterpret_cast<uint2*>(g_cb + (size_t)warp * DDIM + (lane + j * 32) * 4) = u;
        s = fmaf(v.x, v.x, fmaf(v.y, v.y, fmaf(v.z, v.z, fmaf(v.w, v.w, s))));
    }
#pragma unroll
    for (int o = 16; o > 0; o >>= 1) s += __shfl_xor_sync(0xffffffffu, s, o);
    if (lane == 0) g_cnorm[warp] = s;
}

// ---------------------------------------------------------------------------
// Main kernel helpers (512 threads = 16 warps; CTA tile 64 x 128)
// ---------------------------------------------------------------------------
// Stage A chunk (64 rows x 128 cols fp32): warp w owns rows 4w..4w+3, 1 float4/lane/row.
__device__ __forceinline__ void ldgA(const float* __restrict__ x, int rowBase, int chunk,
                                     int wid, int lane, float4 v[4]) {
#pragma unroll
    for (int i = 0; i < 4; i++) {
        int row = wid * 4 + i;
        v[i] = *reinterpret_cast<const float4*>(
            x + (size_t)(rowBase + row) * DDIM + chunk * 128 + lane * 4);
    }
}

__device__ __forceinline__ void stsA(char* smem, uint32_t aoff, float* sxn,
                                     int wid, int lane, const float4 v[4]) {
#pragma unroll
    for (int i = 0; i < 4; i++) {
        int row = wid * 4 + i;
        __nv_bfloat162 lo = __float22bfloat162_rn(make_float2(v[i].x, v[i].y));
        __nv_bfloat162 hi = __float22bfloat162_rn(make_float2(v[i].z, v[i].w));
        uint2 u;
        u.x = *reinterpret_cast<uint32_t*>(&lo);
        u.y = *reinterpret_cast<uint32_t*>(&hi);
        *reinterpret_cast<uint2*>(smem + aoff + (uint32_t)row * SB + (uint32_t)lane * 8u) = u;
        float s = fmaf(v[i].x, v[i].x, fmaf(v[i].y, v[i].y,
                  fmaf(v[i].z, v[i].z, v[i].w * v[i].w)));
#pragma unroll
        for (int o = 16; o > 0; o >>= 1) s += __shfl_xor_sync(0xffffffffu, s, o);
        if (lane == 0) sxn[row] += s;   // warp w owns row 4w+i every chunk: no race
    }
}

// Async-copy B chunk (128 rows x 128 bf16 = 2048 16B units); 4 per thread @512thr.
__device__ __forceinline__ void cpB(uint32_t su, uint32_t boff, int chunk, int tid) {
#pragma unroll
    for (int i = 0; i < 4; i++) {
        int unit = tid + i * 512;
        int row = unit >> 4;
        int u   = unit & 15;
        const __nv_bfloat16* src = g_cb + (size_t)row * DDIM + chunk * 128 + u * 8;
        CP_ASYNC16(su + boff + (uint32_t)row * SB + (uint32_t)u * 16u, src);
    }
}

// MMA over one K=128 chunk: warp tile 16(m) x 32(n), 8 k-steps of 16.
__device__ __forceinline__ void mma_chunk(uint32_t su, uint32_t aoff, uint32_t boff,
                                          int mbase, int nbase, int lane,
                                          float acc[4][4]) {
    const uint32_t koff = (uint32_t)(lane >> 4) * 16u;
    const int lrow = lane & 15;
    uint32_t aaddr = su + aoff + (uint32_t)(mbase + lrow) * SB + koff;
    uint32_t baddr[2];
#pragma unroll
    for (int f = 0; f < 2; f++)
        baddr[f] = su + boff + (uint32_t)(nbase + f * 16 + lrow) * SB + koff;

#pragma unroll
    for (int kk = 0; kk < 8; kk++) {
        const uint32_t kb = (uint32_t)kk * 32u;
        uint32_t a[4], br[2][4];
        LDMATRIX_X4(a[0], a[1], a[2], a[3], aaddr + kb);
#pragma unroll
        for (int f = 0; f < 2; f++)
            LDMATRIX_X4(br[f][0], br[f][1], br[f][2], br[f][3], baddr[f] + kb);
#pragma unroll
        for (int fn = 0; fn < 4; fn++) {
            const int bi = fn >> 1, sub = fn & 1;
            MMA_BF16(acc[fn], a, br[bi][sub], br[bi][sub + 2]);
        }
    }
}

// ---------------------------------------------------------------------------
// Main kernel: 128 CTAs x 512 thr (16 warps), tile 64 x 128, K piped (4x128).
// ---------------------------------------------------------------------------
__global__ __launch_bounds__(512, 1) void kmeans_dist_kernel(const float* __restrict__ x,
                                                             float* __restrict__ out) {
    extern __shared__ char smem[];
    const uint32_t su = smem_u32_of(smem);
    const int tid  = threadIdx.x;
    const int wid  = tid >> 5;
    const int lane = tid & 31;
    const int rowBase = blockIdx.x * 64;

    float* sxn = reinterpret_cast<float*>(smem + SM_XN);
    float* scn = reinterpret_cast<float*>(smem + SM_CN);
    if (tid < 64)  sxn[tid] = 0.0f;
    if (tid >= 128 && tid < 256) scn[tid - 128] = g_cnorm[tid - 128];
    __syncthreads();

    const int mbase = (wid >> 2) * 16;     // 0,16,32,48
    const int nbase = (wid & 3) * 32;      // 0,32,64,96

    float acc[4][4];
#pragma unroll
    for (int j = 0; j < 4; j++)
#pragma unroll
        for (int q = 0; q < 4; q++) acc[j][q] = 0.0f;

    float4 st[4];

    // ---- prologue ----
    ldgA(x, rowBase, 0, wid, lane, st);
    cpB(su, SM_B0, 0, tid); CP_COMMIT();          // g0
    cpB(su, SM_B1, 1, tid); CP_COMMIT();          // g1
    stsA(smem, SM_A0, sxn, wid, lane, st);
    CP_WAIT(1); __syncthreads();                  // B0 + A0 ready

    // ---- chunk 0 ----
    ldgA(x, rowBase, 1, wid, lane, st);           // overlaps MMA
    mma_chunk(su, SM_A0, SM_B0, mbase, nbase, lane, acc);
    __syncthreads();                              // done reading A0/B0
    stsA(smem, SM_A1, sxn, wid, lane, st);
    cpB(su, SM_B0, 2, tid); CP_COMMIT();          // g2
    CP_WAIT(1); __syncthreads();                  // B1 + A1 ready

    // ---- chunk 1 ----
    ldgA(x, rowBase, 2, wid, lane, st);
    mma_chunk(su, SM_A1, SM_B1, mbase, nbase, lane, acc);
    __syncthreads();
    stsA(smem, SM_A0, sxn, wid, lane, st);
    cpB(su, SM_B1, 3, tid); CP_COMMIT();          // g3
    CP_WAIT(1); __syncthreads();                  // B0(c2) + A0(c2) ready

    // ---- chunk 2 ----
    ldgA(x, rowBase, 3, wid, lane, st);
    mma_chunk(su, SM_A0, SM_B0, mbase, nbase, lane, acc);
    __syncthreads();
    stsA(smem, SM_A1, sxn, wid, lane, st);
    CP_WAIT(0); __syncthreads();                  // B1(c3) + A1(c3) ready

    // ---- chunk 3 ----
    mma_chunk(su, SM_A1, SM_B1, mbase, nbase, lane, acc);

    // ---- epilogue: dist = sqrt(max(xn + cn - 2*dot, 0)) ----
    const int qrow = lane >> 2;
    const int qcol = (lane & 3) * 2;
    const int r0 = mbase + qrow;
    const float xn0 = sxn[r0];
    const float xn1 = sxn[r0 + 8];
#pragma unroll
    for (int fn = 0; fn < 4; fn++) {
        const int c = nbase + fn * 8 + qcol;
        const float cn0 = scn[c];
        const float cn1 = scn[c + 1];
        float2 o0, o1;
        o0.x = sqrtf(fmaxf(xn0 + cn0 - 2.0f * acc[fn][0], 0.0f));
        o0.y = sqrtf(fmaxf(xn0 + cn1 - 2.0f * acc[fn][1], 0.0f));
        o1.x = sqrtf(fmaxf(xn1 + cn0 - 2.0f * acc[fn][2], 0.0f));
        o1.y = sqrtf(fmaxf(xn1 + cn1 - 2.0f * acc[fn][3], 0.0f));
        *reinterpret_cast<float2*>(out + (size_t)(rowBase + r0) * KCEN + c)     = o0;
        *reinterpret_cast<float2*>(out + (size_t)(rowBase + r0 + 8) * KCEN + c) = o1;
    }
}

extern "C" void kernel_launch(void* const* d_in, const int* in_sizes, int n_in,
                              void* d_out, int out_size) {
    const float* x   = (const float*)d_in[0];
    const float* cen = (const float*)d_in[1];
    float* out = (float*)d_out;

    cudaFuncSetAttribute(kmeans_dist_kernel,
                         cudaFuncAttributeMaxDynamicSharedMemorySize, SM_TOTAL);

    cen_prep_kernel<<<16, 256>>>(cen);                       // 128 warps, one per centroid
    kmeans_dist_kernel<<<128, 512, SM_TOTAL>>>(x, out);      // 8192/64 rows
}